// round 9
// baseline (speedup 1.0000x reference)
#include <cuda_runtime.h>
#include <cstdint>

// ---------------------------------------------------------------------------
// SelfAttention: out = LN( softmax(XWq (XWk)^T / sqrt(D)) (XWv) + X )
// B=4, N=4096, D=512  (fp32 in/out, TF32 tensor-core GEMMs inside)
//
// Scratch kept to ~115 MB of static __device__ arrays (R5 failed at module
// load with 392 MB -> CUDA 802 "system not yet initialized" on this GB300).
// Scores are processed per (batch, 1024-row chunk) through one 16 MB buffer;
// the attention output overwrites the (dead) Q rows of its chunk.
// ---------------------------------------------------------------------------

#define BM 128
#define BN 128
#define BK 16
#define KPAD 20          // BK + 4 pad -> conflict-free fragment LDS

#define CHUNK 1024       // S-rows processed per pass

// Scratch (static __device__ arrays: allocation-free per harness rules)
__device__ float g_Wt[3 * 512 * 512];        //  3 MB  Wq^T, Wk^T, Wv^T
__device__ float g_Q [16384 * 512];          // 32 MB  Q, then reused as att
__device__ float g_K [16384 * 512];          // 32 MB
__device__ float g_Vt[512 * 16384];          // 32 MB  V transposed: [e][b*4096+m]
__device__ float g_S [CHUNK * 4096];         // 16 MB  one score chunk

// ---------------------------------------------------------------------------
// helpers
// ---------------------------------------------------------------------------
__device__ __forceinline__ float ftf32(float x) {
    uint32_t u;
    asm("cvt.rna.tf32.f32 %0, %1;" : "=r"(u) : "f"(x));
    return __uint_as_float(u);
}
__device__ __forceinline__ float4 f4tf32(float4 v) {
    v.x = ftf32(v.x); v.y = ftf32(v.y); v.z = ftf32(v.z); v.w = ftf32(v.w);
    return v;
}

__device__ __forceinline__ void mma8(float c[4], const float a[4], const float b[2]) {
    asm volatile(
        "mma.sync.aligned.m16n8k8.row.col.f32.tf32.tf32.f32 "
        "{%0,%1,%2,%3}, {%4,%5,%6,%7}, {%8,%9}, {%0,%1,%2,%3};\n"
        : "+f"(c[0]), "+f"(c[1]), "+f"(c[2]), "+f"(c[3])
        : "r"(__float_as_uint(a[0])), "r"(__float_as_uint(a[1])),
          "r"(__float_as_uint(a[2])), "r"(__float_as_uint(a[3])),
          "r"(__float_as_uint(b[0])), "r"(__float_as_uint(b[1])));
}

// ---------------------------------------------------------------------------
// weight transpose: Wt[z][e][d] = W_z[d][e]   (512x512 each, z = q/k/v)
// ---------------------------------------------------------------------------
__global__ void transpose512(const float* __restrict__ W0,
                             const float* __restrict__ W1,
                             const float* __restrict__ W2) {
    const float* W = (blockIdx.z == 0) ? W0 : (blockIdx.z == 1) ? W1 : W2;
    float* O = g_Wt + (long long)blockIdx.z * 512 * 512;
    __shared__ float tile[32][33];
    int xi = blockIdx.x * 32 + threadIdx.x;
    int yi = blockIdx.y * 32 + threadIdx.y;
#pragma unroll
    for (int j = 0; j < 32; j += 8)
        tile[threadIdx.y + j][threadIdx.x] = W[(yi + j) * 512 + xi];
    __syncthreads();
    int xo = blockIdx.y * 32 + threadIdx.x;
    int yo = blockIdx.x * 32 + threadIdx.y;
#pragma unroll
    for (int j = 0; j < 32; j += 8)
        O[(yo + j) * 512 + xo] = tile[threadIdx.x][threadIdx.y + j];
}

// ---------------------------------------------------------------------------
// Generic TF32 GEMM:  C = alpha * A @ B
//   A row-major [M,K]  (A[m*lda + k])
//   B stored as [N,K]  (B[n*ldb + k])  -> computes A @ B_storage^T
//   C row-major [M,N], ldc
//   batch via blockIdx.z with element strides sA/sB/sC.
// CTA tile 128x128x16, 8 warps = 2(M) x 4(N), warp tile 64x32 of m16n8k8.
// All problem dims are multiples of the tiles -> no bounds checks.
// ---------------------------------------------------------------------------
__global__ __launch_bounds__(256) void gemm_tf32(
    const float* __restrict__ A, int lda, long long sA,
    const float* __restrict__ B, int ldb, long long sB,
    float* __restrict__ C, int ldc, long long sC,
    int K, float alpha)
{
    __shared__ float As[BM][KPAD];
    __shared__ float Bs[BN][KPAD];

    A += (long long)blockIdx.z * sA;
    B += (long long)blockIdx.z * sB;
    C += (long long)blockIdx.z * sC;
    const int m0 = blockIdx.y * BM;
    const int n0 = blockIdx.x * BN;

    const int tid  = threadIdx.x;
    const int lane = tid & 31;
    const int warp = tid >> 5;
    const int wm = (warp & 1) * 64;   // warp M offset in CTA tile
    const int wn = (warp >> 1) * 32;  // warp N offset
    const int g  = lane >> 2;         // groupID
    const int t4 = lane & 3;          // threadID in group

    // staging: each thread moves 2 float4 per matrix per k-tile
    const int r = tid >> 2;           // 0..63 (row within tile, +64 second pass)
    const int q = (tid & 3) * 4;      // k-chunk offset

    const float* Ag0 = A + (long long)(m0 + r)      * lda + q;
    const float* Ag1 = A + (long long)(m0 + r + 64) * lda + q;
    const float* Bg0 = B + (long long)(n0 + r)      * ldb + q;
    const float* Bg1 = B + (long long)(n0 + r + 64) * ldb + q;

    float c[4][4][4];
#pragma unroll
    for (int mt = 0; mt < 4; mt++)
#pragma unroll
        for (int nt = 0; nt < 4; nt++)
#pragma unroll
            for (int i = 0; i < 4; i++) c[mt][nt][i] = 0.0f;

    float4 pa0 = *(const float4*)Ag0;
    float4 pa1 = *(const float4*)Ag1;
    float4 pb0 = *(const float4*)Bg0;
    float4 pb1 = *(const float4*)Bg1;

    const int KT = K / BK;
    for (int kt = 0; kt < KT; kt++) {
        // commit staged tile to smem (TF32-rounded)
        *(float4*)&As[r][q]      = f4tf32(pa0);
        *(float4*)&As[r + 64][q] = f4tf32(pa1);
        *(float4*)&Bs[r][q]      = f4tf32(pb0);
        *(float4*)&Bs[r + 64][q] = f4tf32(pb1);
        __syncthreads();

        // prefetch next tile into registers (overlaps with compute below)
        if (kt + 1 < KT) {
            const int ko = (kt + 1) * BK;
            pa0 = *(const float4*)(Ag0 + ko);
            pa1 = *(const float4*)(Ag1 + ko);
            pb0 = *(const float4*)(Bg0 + ko);
            pb1 = *(const float4*)(Bg1 + ko);
        }

#pragma unroll
        for (int kk = 0; kk < BK; kk += 8) {
            float a[4][4];
            float bf[4][2];
#pragma unroll
            for (int mt = 0; mt < 4; mt++) {
                const int row = wm + mt * 16;
                a[mt][0] = As[row + g    ][kk + t4];
                a[mt][1] = As[row + g + 8][kk + t4];
                a[mt][2] = As[row + g    ][kk + t4 + 4];
                a[mt][3] = As[row + g + 8][kk + t4 + 4];
            }
#pragma unroll
            for (int nt = 0; nt < 4; nt++) {
                const int col = wn + nt * 8 + g;
                bf[nt][0] = Bs[col][kk + t4];
                bf[nt][1] = Bs[col][kk + t4 + 4];
            }
#pragma unroll
            for (int mt = 0; mt < 4; mt++)
#pragma unroll
                for (int nt = 0; nt < 4; nt++)
                    mma8(c[mt][nt], a[mt], bf[nt]);
        }
        __syncthreads();
    }

    // epilogue: scaled float2 stores
#pragma unroll
    for (int mt = 0; mt < 4; mt++) {
#pragma unroll
        for (int nt = 0; nt < 4; nt++) {
            const int row = m0 + wm + mt * 16 + g;
            const int col = n0 + wn + nt * 8 + t4 * 2;
            float2 v0 = make_float2(alpha * c[mt][nt][0], alpha * c[mt][nt][1]);
            float2 v1 = make_float2(alpha * c[mt][nt][2], alpha * c[mt][nt][3]);
            *(float2*)&C[(long long)row * ldc + col]       = v0;
            *(float2*)&C[(long long)(row + 8) * ldc + col] = v1;
        }
    }
}

// ---------------------------------------------------------------------------
// row softmax over 4096 elements, in place. one CTA (256 threads) per row.
// ---------------------------------------------------------------------------
__global__ __launch_bounds__(256) void softmax4096(float* __restrict__ S) {
    float4* row = reinterpret_cast<float4*>(S) + (long long)blockIdx.x * 1024;
    const int tid = threadIdx.x;
    float4 v[4];
    float mx = -3.0e38f;
#pragma unroll
    for (int i = 0; i < 4; i++) {
        v[i] = row[tid + i * 256];
        mx = fmaxf(mx, fmaxf(fmaxf(v[i].x, v[i].y), fmaxf(v[i].z, v[i].w)));
    }
    __shared__ float red[8];
#pragma unroll
    for (int o = 16; o; o >>= 1) mx = fmaxf(mx, __shfl_xor_sync(0xffffffffu, mx, o));
    if ((tid & 31) == 0) red[tid >> 5] = mx;
    __syncthreads();
    if (tid < 32) {
        float t = (tid < 8) ? red[tid] : -3.0e38f;
#pragma unroll
        for (int o = 4; o; o >>= 1) t = fmaxf(t, __shfl_xor_sync(0xffffffffu, t, o));
        if (tid == 0) red[0] = t;
    }
    __syncthreads();
    mx = red[0];
    __syncthreads();

    float sum = 0.0f;
#pragma unroll
    for (int i = 0; i < 4; i++) {
        v[i].x = __expf(v[i].x - mx);
        v[i].y = __expf(v[i].y - mx);
        v[i].z = __expf(v[i].z - mx);
        v[i].w = __expf(v[i].w - mx);
        sum += (v[i].x + v[i].y) + (v[i].z + v[i].w);
    }
#pragma unroll
    for (int o = 16; o; o >>= 1) sum += __shfl_xor_sync(0xffffffffu, sum, o);
    if ((tid & 31) == 0) red[tid >> 5] = sum;
    __syncthreads();
    if (tid < 32) {
        float t = (tid < 8) ? red[tid] : 0.0f;
#pragma unroll
        for (int o = 4; o; o >>= 1) t += __shfl_xor_sync(0xffffffffu, t, o);
        if (tid == 0) red[0] = t;
    }
    __syncthreads();
    const float inv = 1.0f / red[0];
#pragma unroll
    for (int i = 0; i < 4; i++) {
        v[i].x *= inv; v[i].y *= inv; v[i].z *= inv; v[i].w *= inv;
        row[tid + i * 256] = v[i];
    }
}

// ---------------------------------------------------------------------------
// out = LayerNorm(att + x) * gamma + beta.  one CTA (128 thr) per token row.
// att lives in g_Q (reused).
// ---------------------------------------------------------------------------
__global__ __launch_bounds__(128) void add_ln(
    const float* __restrict__ att, const float* __restrict__ x,
    const float* __restrict__ gamma, const float* __restrict__ beta,
    float* __restrict__ out)
{
    const long long off = (long long)blockIdx.x * 512;
    const int tid = threadIdx.x;
    float4 a  = reinterpret_cast<const float4*>(att + off)[tid];
    float4 xv = reinterpret_cast<const float4*>(x + off)[tid];
    float4 h = make_float4(a.x + xv.x, a.y + xv.y, a.z + xv.z, a.w + xv.w);
    float s  = (h.x + h.y) + (h.z + h.w);
    float ss = h.x * h.x + h.y * h.y + h.z * h.z + h.w * h.w;
#pragma unroll
    for (int o = 16; o; o >>= 1) {
        s  += __shfl_xor_sync(0xffffffffu, s,  o);
        ss += __shfl_xor_sync(0xffffffffu, ss, o);
    }
    __shared__ float rs[4], rq[4];
    if ((tid & 31) == 0) { rs[tid >> 5] = s; rq[tid >> 5] = ss; }
    __syncthreads();
    const float S  = rs[0] + rs[1] + rs[2] + rs[3];
    const float SS = rq[0] + rq[1] + rq[2] + rq[3];
    const float mean = S * (1.0f / 512.0f);
    const float var  = SS * (1.0f / 512.0f) - mean * mean;
    const float rstd = rsqrtf(var + 1e-5f);
    const float4 gv = reinterpret_cast<const float4*>(gamma)[tid];
    const float4 bv = reinterpret_cast<const float4*>(beta)[tid];
    float4 o4;
    o4.x = (h.x - mean) * rstd * gv.x + bv.x;
    o4.y = (h.y - mean) * rstd * gv.y + bv.y;
    o4.z = (h.z - mean) * rstd * gv.z + bv.z;
    o4.w = (h.w - mean) * rstd * gv.w + bv.w;
    reinterpret_cast<float4*>(out + off)[tid] = o4;
}

// ---------------------------------------------------------------------------
// launch
// ---------------------------------------------------------------------------
extern "C" void kernel_launch(void* const* d_in, const int* in_sizes, int n_in,
                              void* d_out, int out_size)
{
    const float* x     = (const float*)d_in[0];  // [4,4096,512]
    const float* Wq    = (const float*)d_in[1];  // [512,512]
    const float* Wk    = (const float*)d_in[2];
    const float* Wv    = (const float*)d_in[3];
    const float* gamma = (const float*)d_in[4];
    const float* beta  = (const float*)d_in[5];
    float* out = (float*)d_out;

    float *Wt, *Q, *Kp, *Vt, *S;
    cudaGetSymbolAddress((void**)&Wt, g_Wt);
    cudaGetSymbolAddress((void**)&Q,  g_Q);
    cudaGetSymbolAddress((void**)&Kp, g_K);
    cudaGetSymbolAddress((void**)&Vt, g_Vt);
    cudaGetSymbolAddress((void**)&S,  g_S);

    // 1) transpose weights (Wt[z] = W_z^T, row-major [e][d])
    transpose512<<<dim3(16, 16, 3), dim3(32, 8)>>>(Wq, Wk, Wv);

    // 2) Q = X @ Wq : M=16384 N=512 K=512.  B[n][k] = Wt_q[n*512+k]
    gemm_tf32<<<dim3(4, 128, 1), 256>>>(x, 512, 0,
                                        Wt, 512, 0,
                                        Q, 512, 0, 512, 1.0f);
    // 3) K = X @ Wk
    gemm_tf32<<<dim3(4, 128, 1), 256>>>(x, 512, 0,
                                        Wt + 512 * 512, 512, 0,
                                        Kp, 512, 0, 512, 1.0f);
    // 4) Vt = Wv^T @ X^T : M=512 N=16384 K=512.  B[n][k] = x[n*512+k]
    gemm_tf32<<<dim3(128, 4, 1), 256>>>(Wt + 2 * 512 * 512, 512, 0,
                                        x, 512, 0,
                                        Vt, 16384, 0, 512, 1.0f);

    // 5) attention, per (batch, 1024-row chunk) through one 16 MB S buffer.
    //    att overwrites the chunk's (dead) Q rows.
    const float inv_sqrt_d = 0.04419417382415922f;   // 1/sqrt(512)
    for (int b = 0; b < 4; b++) {
        for (int c = 0; c < 4; c++) {
            float* Qc = Q + ((long long)b * 4096 + c * CHUNK) * 512;
            // S = (Q_chunk K_b^T) / sqrt(D) : M=1024 N=4096 K=512
            gemm_tf32<<<dim3(32, CHUNK / BM, 1), 256>>>(
                Qc, 512, 0,
                Kp + (long long)b * 4096 * 512, 512, 0,
                S, 4096, 0, 512, inv_sqrt_d);
            // row softmax in place
            softmax4096<<<CHUNK, 256>>>(S);
            // att_chunk = P @ V_b : M=1024 N=512 K=4096
            //   B[n=e][k=m] = Vt[e*16384 + b*4096 + m]
            gemm_tf32<<<dim3(4, CHUNK / BM, 1), 256>>>(
                S, 4096, 0,
                Vt + (long long)b * 4096, 16384, 0,
                Qc, 512, 0, 4096, 1.0f);
        }
    }

    // 6) residual + LayerNorm (att lives in g_Q)
    add_ln<<<16384, 128>>>(Q, x, gamma, beta, out);
}

// round 10
// speedup vs baseline: 2.3378x; 2.3378x over previous
#include <cuda_runtime.h>
#include <cstdint>

// ---------------------------------------------------------------------------
// SelfAttention: out = LN( softmax(XWq (XWk)^T / sqrt(D)) (XWv) + X )
// B=4, N=4096, D=512  (fp32 in/out, TF32 tensor-core GEMMs inside)
//
// R9 -> R10:
//  * attention chunk loop batches all 4 batches via blockIdx.z
//    (52 -> 16 launches, PV grid 32 -> 128 CTAs)
//  * GEMM smem double-buffered: 1 sync per k-tile, prefetch->compute->commit
//  * static scratch 163 MB (R9: 115 MB OK, R5: 392 MB failed module load)
// ---------------------------------------------------------------------------

#define BM 128
#define BN 128
#define BK 16
#define KPAD 20          // BK + 4 pad -> conflict-free fragment LDS

#define CHUNK 1024       // S-rows per batch per pass

// Scratch (static __device__ arrays: allocation-free per harness rules)
__device__ float g_Wt[3 * 512 * 512];        //  3 MB  Wq^T, Wk^T, Wv^T
__device__ float g_Q [16384 * 512];          // 32 MB  Q, then reused as att
__device__ float g_K [16384 * 512];          // 32 MB
__device__ float g_Vt[512 * 16384];          // 32 MB  V transposed: [e][b*4096+m]
__device__ float g_S [4 * CHUNK * 4096];     // 64 MB  score chunk, all batches

// ---------------------------------------------------------------------------
// helpers
// ---------------------------------------------------------------------------
__device__ __forceinline__ float ftf32(float x) {
    uint32_t u;
    asm("cvt.rna.tf32.f32 %0, %1;" : "=r"(u) : "f"(x));
    return __uint_as_float(u);
}
__device__ __forceinline__ float4 f4tf32(float4 v) {
    v.x = ftf32(v.x); v.y = ftf32(v.y); v.z = ftf32(v.z); v.w = ftf32(v.w);
    return v;
}

__device__ __forceinline__ void mma8(float c[4], const float a[4], const float b[2]) {
    asm volatile(
        "mma.sync.aligned.m16n8k8.row.col.f32.tf32.tf32.f32 "
        "{%0,%1,%2,%3}, {%4,%5,%6,%7}, {%8,%9}, {%0,%1,%2,%3};\n"
        : "+f"(c[0]), "+f"(c[1]), "+f"(c[2]), "+f"(c[3])
        : "r"(__float_as_uint(a[0])), "r"(__float_as_uint(a[1])),
          "r"(__float_as_uint(a[2])), "r"(__float_as_uint(a[3])),
          "r"(__float_as_uint(b[0])), "r"(__float_as_uint(b[1])));
}

// ---------------------------------------------------------------------------
// weight transpose: Wt[z][e][d] = W_z[d][e]   (512x512 each, z = q/k/v)
// ---------------------------------------------------------------------------
__global__ void transpose512(const float* __restrict__ W0,
                             const float* __restrict__ W1,
                             const float* __restrict__ W2) {
    const float* W = (blockIdx.z == 0) ? W0 : (blockIdx.z == 1) ? W1 : W2;
    float* O = g_Wt + (long long)blockIdx.z * 512 * 512;
    __shared__ float tile[32][33];
    int xi = blockIdx.x * 32 + threadIdx.x;
    int yi = blockIdx.y * 32 + threadIdx.y;
#pragma unroll
    for (int j = 0; j < 32; j += 8)
        tile[threadIdx.y + j][threadIdx.x] = W[(yi + j) * 512 + xi];
    __syncthreads();
    int xo = blockIdx.y * 32 + threadIdx.x;
    int yo = blockIdx.x * 32 + threadIdx.y;
#pragma unroll
    for (int j = 0; j < 32; j += 8)
        O[(yo + j) * 512 + xo] = tile[threadIdx.x][threadIdx.y + j];
}

// ---------------------------------------------------------------------------
// Generic TF32 GEMM:  C = alpha * A @ B_storage^T
//   A row-major [M,K]  (A[m*lda + k])
//   B stored as [N,K]  (B[n*ldb + k])
//   C row-major [M,N], ldc
//   batch via blockIdx.z with element strides sA/sB/sC.
// CTA tile 128x128x16, 8 warps = 2(M) x 4(N), warp tile 64x32 of m16n8k8.
// Double-buffered smem: prefetch(global) -> compute(cur) -> commit(nxt) -> sync.
// All problem dims are multiples of the tiles -> no bounds checks.
// ---------------------------------------------------------------------------
__global__ __launch_bounds__(256) void gemm_tf32(
    const float* __restrict__ A, int lda, long long sA,
    const float* __restrict__ B, int ldb, long long sB,
    float* __restrict__ C, int ldc, long long sC,
    int K, float alpha)
{
    __shared__ float As[2][BM][KPAD];
    __shared__ float Bs[2][BN][KPAD];

    A += (long long)blockIdx.z * sA;
    B += (long long)blockIdx.z * sB;
    C += (long long)blockIdx.z * sC;
    const int m0 = blockIdx.y * BM;
    const int n0 = blockIdx.x * BN;

    const int tid  = threadIdx.x;
    const int lane = tid & 31;
    const int warp = tid >> 5;
    const int wm = (warp & 1) * 64;   // warp M offset in CTA tile
    const int wn = (warp >> 1) * 32;  // warp N offset
    const int g  = lane >> 2;         // groupID
    const int t4 = lane & 3;          // threadID in group

    // staging: each thread moves 2 float4 per matrix per k-tile
    const int r = tid >> 2;           // 0..63 (row within tile, +64 second pass)
    const int q = (tid & 3) * 4;      // k-chunk offset

    const float* Ag0 = A + (long long)(m0 + r)      * lda + q;
    const float* Ag1 = A + (long long)(m0 + r + 64) * lda + q;
    const float* Bg0 = B + (long long)(n0 + r)      * ldb + q;
    const float* Bg1 = B + (long long)(n0 + r + 64) * ldb + q;

    float c[4][4][4];
#pragma unroll
    for (int mt = 0; mt < 4; mt++)
#pragma unroll
        for (int nt = 0; nt < 4; nt++)
#pragma unroll
            for (int i = 0; i < 4; i++) c[mt][nt][i] = 0.0f;

    // stage k-tile 0
    float4 pa0 = *(const float4*)Ag0;
    float4 pa1 = *(const float4*)Ag1;
    float4 pb0 = *(const float4*)Bg0;
    float4 pb1 = *(const float4*)Bg1;
    *(float4*)&As[0][r][q]      = f4tf32(pa0);
    *(float4*)&As[0][r + 64][q] = f4tf32(pa1);
    *(float4*)&Bs[0][r][q]      = f4tf32(pb0);
    *(float4*)&Bs[0][r + 64][q] = f4tf32(pb1);
    __syncthreads();

    const int KT = K / BK;
    for (int kt = 0; kt < KT; kt++) {
        const int cur = kt & 1;

        // prefetch next tile into registers (overlaps with compute below)
        if (kt + 1 < KT) {
            const int ko = (kt + 1) * BK;
            pa0 = *(const float4*)(Ag0 + ko);
            pa1 = *(const float4*)(Ag1 + ko);
            pb0 = *(const float4*)(Bg0 + ko);
            pb1 = *(const float4*)(Bg1 + ko);
        }

#pragma unroll
        for (int kk = 0; kk < BK; kk += 8) {
            float a[4][4];
            float bf[4][2];
#pragma unroll
            for (int mt = 0; mt < 4; mt++) {
                const int row = wm + mt * 16;
                a[mt][0] = As[cur][row + g    ][kk + t4];
                a[mt][1] = As[cur][row + g + 8][kk + t4];
                a[mt][2] = As[cur][row + g    ][kk + t4 + 4];
                a[mt][3] = As[cur][row + g + 8][kk + t4 + 4];
            }
#pragma unroll
            for (int nt = 0; nt < 4; nt++) {
                const int col = wn + nt * 8 + g;
                bf[nt][0] = Bs[cur][col][kk + t4];
                bf[nt][1] = Bs[cur][col][kk + t4 + 4];
            }
#pragma unroll
            for (int mt = 0; mt < 4; mt++)
#pragma unroll
                for (int nt = 0; nt < 4; nt++)
                    mma8(c[mt][nt], a[mt], bf[nt]);
        }

        // commit prefetched tile to the other buffer
        if (kt + 1 < KT) {
            const int nxt = cur ^ 1;
            *(float4*)&As[nxt][r][q]      = f4tf32(pa0);
            *(float4*)&As[nxt][r + 64][q] = f4tf32(pa1);
            *(float4*)&Bs[nxt][r][q]      = f4tf32(pb0);
            *(float4*)&Bs[nxt][r + 64][q] = f4tf32(pb1);
            __syncthreads();
        }
    }

    // epilogue: scaled float2 stores
#pragma unroll
    for (int mt = 0; mt < 4; mt++) {
#pragma unroll
        for (int nt = 0; nt < 4; nt++) {
            const int row = m0 + wm + mt * 16 + g;
            const int col = n0 + wn + nt * 8 + t4 * 2;
            float2 v0 = make_float2(alpha * c[mt][nt][0], alpha * c[mt][nt][1]);
            float2 v1 = make_float2(alpha * c[mt][nt][2], alpha * c[mt][nt][3]);
            *(float2*)&C[(long long)row * ldc + col]       = v0;
            *(float2*)&C[(long long)(row + 8) * ldc + col] = v1;
        }
    }
}

// ---------------------------------------------------------------------------
// row softmax over 4096 elements, in place. one CTA (256 threads) per row.
// ---------------------------------------------------------------------------
__global__ __launch_bounds__(256) void softmax4096(float* __restrict__ S) {
    float4* row = reinterpret_cast<float4*>(S) + (long long)blockIdx.x * 1024;
    const int tid = threadIdx.x;
    float4 v[4];
    float mx = -3.0e38f;
#pragma unroll
    for (int i = 0; i < 4; i++) {
        v[i] = row[tid + i * 256];
        mx = fmaxf(mx, fmaxf(fmaxf(v[i].x, v[i].y), fmaxf(v[i].z, v[i].w)));
    }
    __shared__ float red[8];
#pragma unroll
    for (int o = 16; o; o >>= 1) mx = fmaxf(mx, __shfl_xor_sync(0xffffffffu, mx, o));
    if ((tid & 31) == 0) red[tid >> 5] = mx;
    __syncthreads();
    if (tid < 32) {
        float t = (tid < 8) ? red[tid] : -3.0e38f;
#pragma unroll
        for (int o = 4; o; o >>= 1) t = fmaxf(t, __shfl_xor_sync(0xffffffffu, t, o));
        if (tid == 0) red[0] = t;
    }
    __syncthreads();
    mx = red[0];
    __syncthreads();

    float sum = 0.0f;
#pragma unroll
    for (int i = 0; i < 4; i++) {
        v[i].x = __expf(v[i].x - mx);
        v[i].y = __expf(v[i].y - mx);
        v[i].z = __expf(v[i].z - mx);
        v[i].w = __expf(v[i].w - mx);
        sum += (v[i].x + v[i].y) + (v[i].z + v[i].w);
    }
#pragma unroll
    for (int o = 16; o; o >>= 1) sum += __shfl_xor_sync(0xffffffffu, sum, o);
    if ((tid & 31) == 0) red[tid >> 5] = sum;
    __syncthreads();
    if (tid < 32) {
        float t = (tid < 8) ? red[tid] : 0.0f;
#pragma unroll
        for (int o = 4; o; o >>= 1) t += __shfl_xor_sync(0xffffffffu, t, o);
        if (tid == 0) red[0] = t;
    }
    __syncthreads();
    const float inv = 1.0f / red[0];
#pragma unroll
    for (int i = 0; i < 4; i++) {
        v[i].x *= inv; v[i].y *= inv; v[i].z *= inv; v[i].w *= inv;
        row[tid + i * 256] = v[i];
    }
}

// ---------------------------------------------------------------------------
// out = LayerNorm(att + x) * gamma + beta.  one CTA (128 thr) per token row.
// att lives in g_Q (reused).
// ---------------------------------------------------------------------------
__global__ __launch_bounds__(128) void add_ln(
    const float* __restrict__ att, const float* __restrict__ x,
    const float* __restrict__ gamma, const float* __restrict__ beta,
    float* __restrict__ out)
{
    const long long off = (long long)blockIdx.x * 512;
    const int tid = threadIdx.x;
    float4 a  = reinterpret_cast<const float4*>(att + off)[tid];
    float4 xv = reinterpret_cast<const float4*>(x + off)[tid];
    float4 h = make_float4(a.x + xv.x, a.y + xv.y, a.z + xv.z, a.w + xv.w);
    float s  = (h.x + h.y) + (h.z + h.w);
    float ss = h.x * h.x + h.y * h.y + h.z * h.z + h.w * h.w;
#pragma unroll
    for (int o = 16; o; o >>= 1) {
        s  += __shfl_xor_sync(0xffffffffu, s,  o);
        ss += __shfl_xor_sync(0xffffffffu, ss, o);
    }
    __shared__ float rs[4], rq[4];
    if ((tid & 31) == 0) { rs[tid >> 5] = s; rq[tid >> 5] = ss; }
    __syncthreads();
    const float S  = rs[0] + rs[1] + rs[2] + rs[3];
    const float SS = rq[0] + rq[1] + rq[2] + rq[3];
    const float mean = S * (1.0f / 512.0f);
    const float var  = SS * (1.0f / 512.0f) - mean * mean;
    const float rstd = rsqrtf(var + 1e-5f);
    const float4 gv = reinterpret_cast<const float4*>(gamma)[tid];
    const float4 bv = reinterpret_cast<const float4*>(beta)[tid];
    float4 o4;
    o4.x = (h.x - mean) * rstd * gv.x + bv.x;
    o4.y = (h.y - mean) * rstd * gv.y + bv.y;
    o4.z = (h.z - mean) * rstd * gv.z + bv.z;
    o4.w = (h.w - mean) * rstd * gv.w + bv.w;
    reinterpret_cast<float4*>(out + off)[tid] = o4;
}

// ---------------------------------------------------------------------------
// launch
// ---------------------------------------------------------------------------
extern "C" void kernel_launch(void* const* d_in, const int* in_sizes, int n_in,
                              void* d_out, int out_size)
{
    const float* x     = (const float*)d_in[0];  // [4,4096,512]
    const float* Wq    = (const float*)d_in[1];  // [512,512]
    const float* Wk    = (const float*)d_in[2];
    const float* Wv    = (const float*)d_in[3];
    const float* gamma = (const float*)d_in[4];
    const float* beta  = (const float*)d_in[5];
    float* out = (float*)d_out;

    float *Wt, *Q, *Kp, *Vt, *S;
    cudaGetSymbolAddress((void**)&Wt, g_Wt);
    cudaGetSymbolAddress((void**)&Q,  g_Q);
    cudaGetSymbolAddress((void**)&Kp, g_K);
    cudaGetSymbolAddress((void**)&Vt, g_Vt);
    cudaGetSymbolAddress((void**)&S,  g_S);

    // 1) transpose weights (Wt[z] = W_z^T, row-major [e][d])
    transpose512<<<dim3(16, 16, 3), dim3(32, 8)>>>(Wq, Wk, Wv);

    // 2) Q = X @ Wq : M=16384 N=512 K=512.  B[n][k] = Wt_q[n*512+k]
    gemm_tf32<<<dim3(4, 128, 1), 256>>>(x, 512, 0,
                                        Wt, 512, 0,
                                        Q, 512, 0, 512, 1.0f);
    // 3) K = X @ Wk
    gemm_tf32<<<dim3(4, 128, 1), 256>>>(x, 512, 0,
                                        Wt + 512 * 512, 512, 0,
                                        Kp, 512, 0, 512, 1.0f);
    // 4) Vt = Wv^T @ X^T : M=512 N=16384 K=512.  B[n][k] = x[n*512+k]
    gemm_tf32<<<dim3(128, 4, 1), 256>>>(Wt + 2 * 512 * 512, 512, 0,
                                        x, 512, 0,
                                        Vt, 16384, 0, 512, 1.0f);

    // 5) attention: 4 chunk passes, all batches batched via blockIdx.z.
    //    S buffer holds [4][CHUNK][4096]; att overwrites the chunk's Q rows.
    const float inv_sqrt_d = 0.04419417382415922f;   // 1/sqrt(512)
    for (int c = 0; c < 4; c++) {
        float* Qc = Q + (long long)c * CHUNK * 512;
        // S[b] = (Q_chunk[b] K_b^T) / sqrt(D) : M=CHUNK N=4096 K=512, z=batch
        gemm_tf32<<<dim3(32, CHUNK / BM, 4), 256>>>(
            Qc, 512, 4096ll * 512,
            Kp, 512, 4096ll * 512,
            S, 4096, (long long)CHUNK * 4096,
            512, inv_sqrt_d);
        // row softmax in place over all 4 batches of this chunk
        softmax4096<<<4 * CHUNK, 256>>>(S);
        // att_chunk[b] = P[b] @ V_b : M=CHUNK N=512 K=4096, z=batch
        //   B[n=e][k=m] = Vt[e*16384 + b*4096 + m]
        gemm_tf32<<<dim3(4, CHUNK / BM, 4), 256>>>(
            S, 4096, (long long)CHUNK * 4096,
            Vt, 16384, 4096,
            Qc, 512, 4096ll * 512,
            4096, 1.0f);
    }

    // 6) residual + LayerNorm (att lives in g_Q)
    add_ln<<<16384, 128>>>(Q, x, gamma, beta, out);
}

// round 14
// speedup vs baseline: 2.9834x; 1.2761x over previous
#include <cuda_runtime.h>
#include <cstdint>

// ---------------------------------------------------------------------------
// SelfAttention: out = LN( softmax(XWq (XWk)^T / sqrt(D)) (XWv) + X )
// B=4, N=4096, D=512  (fp32 in/out, TF32 tensor-core GEMMs inside)
//
// R13 -> R14: FIX illegal access — split-K partial output (C1 = g_P1) was
// addressed with the full-attention batch stride (4096*512) instead of its
// own (CHUNK*512), overrunning the 8 MB buffer for bz>=1. GEMM now takes
// separate sC0/sC1 batch strides. Design otherwise identical to R11:
//  * 4 warps x (64x64 warp tile): 128 B smem per MMA (was 192)
//  * PV split-K=2 via blockIdx.z (grid 128 -> 256 CTAs)
//  * merged Q|K projection launch
// ---------------------------------------------------------------------------

#define BM 128
#define BN 128
#define BK 16
#define KPAD 20          // BK + 4 pad -> conflict-free fragment LDS

#define CHUNK 1024       // S-rows per batch per pass

// Scratch (static __device__ arrays: allocation-free per harness rules)
__device__ float g_Wt[3 * 512 * 512];        //  3 MB  Wq^T, Wk^T, Wv^T
__device__ float g_QK[2 * 16384 * 512];      // 64 MB  Q then att | K
__device__ float g_Vt[512 * 16384];          // 32 MB  V transposed: [e][b*4096+m]
__device__ float g_S [4 * CHUNK * 4096];     // 64 MB  score chunk, all batches
__device__ float g_P1[4 * CHUNK * 512];      //  8 MB  PV split-K partial 1

// ---------------------------------------------------------------------------
// helpers
// ---------------------------------------------------------------------------
__device__ __forceinline__ float ftf32(float x) {
    uint32_t u;
    asm("cvt.rna.tf32.f32 %0, %1;" : "=r"(u) : "f"(x));
    return __uint_as_float(u);
}
__device__ __forceinline__ float4 f4tf32(float4 v) {
    v.x = ftf32(v.x); v.y = ftf32(v.y); v.z = ftf32(v.z); v.w = ftf32(v.w);
    return v;
}

__device__ __forceinline__ void mma8(float c[4], const float a[4], const float b[2]) {
    asm volatile(
        "mma.sync.aligned.m16n8k8.row.col.f32.tf32.tf32.f32 "
        "{%0,%1,%2,%3}, {%4,%5,%6,%7}, {%8,%9}, {%0,%1,%2,%3};\n"
        : "+f"(c[0]), "+f"(c[1]), "+f"(c[2]), "+f"(c[3])
        : "r"(__float_as_uint(a[0])), "r"(__float_as_uint(a[1])),
          "r"(__float_as_uint(a[2])), "r"(__float_as_uint(a[3])),
          "r"(__float_as_uint(b[0])), "r"(__float_as_uint(b[1])));
}

// ---------------------------------------------------------------------------
// weight transpose: Wt[z][e][d] = W_z[d][e]   (512x512 each, z = q/k/v)
// ---------------------------------------------------------------------------
__global__ void transpose512(const float* __restrict__ W0,
                             const float* __restrict__ W1,
                             const float* __restrict__ W2) {
    const float* W = (blockIdx.z == 0) ? W0 : (blockIdx.z == 1) ? W1 : W2;
    float* O = g_Wt + (long long)blockIdx.z * 512 * 512;
    __shared__ float tile[32][33];
    int xi = blockIdx.x * 32 + threadIdx.x;
    int yi = blockIdx.y * 32 + threadIdx.y;
#pragma unroll
    for (int j = 0; j < 32; j += 8)
        tile[threadIdx.y + j][threadIdx.x] = W[(yi + j) * 512 + xi];
    __syncthreads();
    int xo = blockIdx.y * 32 + threadIdx.x;
    int yo = blockIdx.x * 32 + threadIdx.y;
#pragma unroll
    for (int j = 0; j < 32; j += 8)
        O[(yo + j) * 512 + xo] = tile[threadIdx.x][threadIdx.y + j];
}

// ---------------------------------------------------------------------------
// Generic TF32 GEMM:  C = alpha * A @ B_storage^T
//   A row-major [M,K]  (A[m*lda + k]),  B stored as [N,K]  (B[n*ldb + k])
//   C row-major [M,N], ldc
//   blockIdx.z encodes batch (z & 3) and k-half (z >> 2):
//     A += b*sA + kh*kOffA;  B += b*sB + kh*kOffB
//     C  = kh ? (C1 + b*sC1) : (C0 + b*sC0)        <-- separate strides (R14)
// CTA tile 128x128x16, 4 warps = 2(M) x 2(N), warp tile 64x64 of m16n8k8.
// Double-buffered smem: prefetch(global) -> compute(cur) -> commit(nxt) -> sync.
// All problem dims are multiples of the tiles -> no bounds checks.
// ---------------------------------------------------------------------------
__global__ __launch_bounds__(128) void gemm_tf32(
    const float* __restrict__ A, int lda, long long sA, long long kOffA,
    const float* __restrict__ B, int ldb, long long sB, long long kOffB,
    float* __restrict__ C0, long long sC0,
    float* __restrict__ C1, long long sC1,
    int ldc, int K, float alpha)
{
    __shared__ float As[2][BM][KPAD];
    __shared__ float Bs[2][BN][KPAD];

    const int bz = blockIdx.z & 3;
    const int kh = blockIdx.z >> 2;
    A += (long long)bz * sA + (long long)kh * kOffA;
    B += (long long)bz * sB + (long long)kh * kOffB;
    float* C = kh ? (C1 + (long long)bz * sC1)
                  : (C0 + (long long)bz * sC0);

    const int m0 = blockIdx.y * BM;
    const int n0 = blockIdx.x * BN;

    const int tid  = threadIdx.x;
    const int lane = tid & 31;
    const int warp = tid >> 5;
    const int wm = (warp & 1) * 64;   // warp M offset in CTA tile
    const int wn = (warp >> 1) * 64;  // warp N offset
    const int g  = lane >> 2;         // groupID
    const int t4 = lane & 3;          // threadID in group

    // staging: 128 threads, each moves 4 float4 per matrix per k-tile
    const int r = tid >> 2;           // 0..31 (+32i covers 128 rows)
    const int q = (tid & 3) * 4;      // k-chunk offset

    const float* Ag = A + (long long)(m0 + r) * lda + q;
    const float* Bg = B + (long long)(n0 + r) * ldb + q;

    float c[4][8][4];
#pragma unroll
    for (int mt = 0; mt < 4; mt++)
#pragma unroll
        for (int nt = 0; nt < 8; nt++)
#pragma unroll
            for (int i = 0; i < 4; i++) c[mt][nt][i] = 0.0f;

    // stage k-tile 0
    float4 pa[4], pb[4];
#pragma unroll
    for (int i = 0; i < 4; i++) {
        pa[i] = *(const float4*)(Ag + (long long)(i * 32) * lda);
        pb[i] = *(const float4*)(Bg + (long long)(i * 32) * ldb);
    }
#pragma unroll
    for (int i = 0; i < 4; i++) {
        *(float4*)&As[0][r + i * 32][q] = f4tf32(pa[i]);
        *(float4*)&Bs[0][r + i * 32][q] = f4tf32(pb[i]);
    }
    __syncthreads();

    const int KT = K / BK;
    for (int kt = 0; kt < KT; kt++) {
        const int cur = kt & 1;

        // prefetch next tile into registers (overlaps with compute below)
        if (kt + 1 < KT) {
            const int ko = (kt + 1) * BK;
#pragma unroll
            for (int i = 0; i < 4; i++) {
                pa[i] = *(const float4*)(Ag + (long long)(i * 32) * lda + ko);
                pb[i] = *(const float4*)(Bg + (long long)(i * 32) * ldb + ko);
            }
        }

#pragma unroll
        for (int kk = 0; kk < BK; kk += 8) {
            float a[4][4];
            float bf[8][2];
#pragma unroll
            for (int mt = 0; mt < 4; mt++) {
                const int row = wm + mt * 16;
                a[mt][0] = As[cur][row + g    ][kk + t4];
                a[mt][1] = As[cur][row + g + 8][kk + t4];
                a[mt][2] = As[cur][row + g    ][kk + t4 + 4];
                a[mt][3] = As[cur][row + g + 8][kk + t4 + 4];
            }
#pragma unroll
            for (int nt = 0; nt < 8; nt++) {
                const int col = wn + nt * 8 + g;
                bf[nt][0] = Bs[cur][col][kk + t4];
                bf[nt][1] = Bs[cur][col][kk + t4 + 4];
            }
#pragma unroll
            for (int mt = 0; mt < 4; mt++)
#pragma unroll
                for (int nt = 0; nt < 8; nt++)
                    mma8(c[mt][nt], a[mt], bf[nt]);
        }

        // commit prefetched tile to the other buffer
        if (kt + 1 < KT) {
            const int nxt = cur ^ 1;
#pragma unroll
            for (int i = 0; i < 4; i++) {
                *(float4*)&As[nxt][r + i * 32][q] = f4tf32(pa[i]);
                *(float4*)&Bs[nxt][r + i * 32][q] = f4tf32(pb[i]);
            }
            __syncthreads();
        }
    }

    // epilogue: scaled float2 stores
#pragma unroll
    for (int mt = 0; mt < 4; mt++) {
#pragma unroll
        for (int nt = 0; nt < 8; nt++) {
            const int row = m0 + wm + mt * 16 + g;
            const int col = n0 + wn + nt * 8 + t4 * 2;
            float2 v0 = make_float2(alpha * c[mt][nt][0], alpha * c[mt][nt][1]);
            float2 v1 = make_float2(alpha * c[mt][nt][2], alpha * c[mt][nt][3]);
            *(float2*)&C[(long long)row * ldc + col]       = v0;
            *(float2*)&C[(long long)(row + 8) * ldc + col] = v1;
        }
    }
}

// ---------------------------------------------------------------------------
// split-K fixup: dst[b] += src[b]  (CHUNK*512 floats per batch)
// ---------------------------------------------------------------------------
__global__ __launch_bounds__(256) void add_partial(
    float* __restrict__ dst, long long dStride,
    const float* __restrict__ src, long long sStride)
{
    const int idx = blockIdx.x * 256 + threadIdx.x;      // float4 index
    float4* d = reinterpret_cast<float4*>(dst + (long long)blockIdx.y * dStride) + idx;
    const float4* s = reinterpret_cast<const float4*>(src + (long long)blockIdx.y * sStride) + idx;
    float4 a = *d, b = *s;
    a.x += b.x; a.y += b.y; a.z += b.z; a.w += b.w;
    *d = a;
}

// ---------------------------------------------------------------------------
// row softmax over 4096 elements, in place. one CTA (256 threads) per row.
// ---------------------------------------------------------------------------
__global__ __launch_bounds__(256) void softmax4096(float* __restrict__ S) {
    float4* row = reinterpret_cast<float4*>(S) + (long long)blockIdx.x * 1024;
    const int tid = threadIdx.x;
    float4 v[4];
    float mx = -3.0e38f;
#pragma unroll
    for (int i = 0; i < 4; i++) {
        v[i] = row[tid + i * 256];
        mx = fmaxf(mx, fmaxf(fmaxf(v[i].x, v[i].y), fmaxf(v[i].z, v[i].w)));
    }
    __shared__ float red[8];
#pragma unroll
    for (int o = 16; o; o >>= 1) mx = fmaxf(mx, __shfl_xor_sync(0xffffffffu, mx, o));
    if ((tid & 31) == 0) red[tid >> 5] = mx;
    __syncthreads();
    if (tid < 32) {
        float t = (tid < 8) ? red[tid] : -3.0e38f;
#pragma unroll
        for (int o = 4; o; o >>= 1) t = fmaxf(t, __shfl_xor_sync(0xffffffffu, t, o));
        if (tid == 0) red[0] = t;
    }
    __syncthreads();
    mx = red[0];
    __syncthreads();

    float sum = 0.0f;
#pragma unroll
    for (int i = 0; i < 4; i++) {
        v[i].x = __expf(v[i].x - mx);
        v[i].y = __expf(v[i].y - mx);
        v[i].z = __expf(v[i].z - mx);
        v[i].w = __expf(v[i].w - mx);
        sum += (v[i].x + v[i].y) + (v[i].z + v[i].w);
    }
#pragma unroll
    for (int o = 16; o; o >>= 1) sum += __shfl_xor_sync(0xffffffffu, sum, o);
    if ((tid & 31) == 0) red[tid >> 5] = sum;
    __syncthreads();
    if (tid < 32) {
        float t = (tid < 8) ? red[tid] : 0.0f;
#pragma unroll
        for (int o = 4; o; o >>= 1) t += __shfl_xor_sync(0xffffffffu, t, o);
        if (tid == 0) red[0] = t;
    }
    __syncthreads();
    const float inv = 1.0f / red[0];
#pragma unroll
    for (int i = 0; i < 4; i++) {
        v[i].x *= inv; v[i].y *= inv; v[i].z *= inv; v[i].w *= inv;
        row[tid + i * 256] = v[i];
    }
}

// ---------------------------------------------------------------------------
// out = LayerNorm(att + x) * gamma + beta.  one CTA (128 thr) per token row.
// att lives in g_QK[0] (reused Q).
// ---------------------------------------------------------------------------
__global__ __launch_bounds__(128) void add_ln(
    const float* __restrict__ att, const float* __restrict__ x,
    const float* __restrict__ gamma, const float* __restrict__ beta,
    float* __restrict__ out)
{
    const long long off = (long long)blockIdx.x * 512;
    const int tid = threadIdx.x;
    float4 a  = reinterpret_cast<const float4*>(att + off)[tid];
    float4 xv = reinterpret_cast<const float4*>(x + off)[tid];
    float4 h = make_float4(a.x + xv.x, a.y + xv.y, a.z + xv.z, a.w + xv.w);
    float s  = (h.x + h.y) + (h.z + h.w);
    float ss = h.x * h.x + h.y * h.y + h.z * h.z + h.w * h.w;
#pragma unroll
    for (int o = 16; o; o >>= 1) {
        s  += __shfl_xor_sync(0xffffffffu, s,  o);
        ss += __shfl_xor_sync(0xffffffffu, ss, o);
    }
    __shared__ float rs[4], rq[4];
    if ((tid & 31) == 0) { rs[tid >> 5] = s; rq[tid >> 5] = ss; }
    __syncthreads();
    const float S  = rs[0] + rs[1] + rs[2] + rs[3];
    const float SS = rq[0] + rq[1] + rq[2] + rq[3];
    const float mean = S * (1.0f / 512.0f);
    const float var  = SS * (1.0f / 512.0f) - mean * mean;
    const float rstd = rsqrtf(var + 1e-5f);
    const float4 gv = reinterpret_cast<const float4*>(gamma)[tid];
    const float4 bv = reinterpret_cast<const float4*>(beta)[tid];
    float4 o4;
    o4.x = (h.x - mean) * rstd * gv.x + bv.x;
    o4.y = (h.y - mean) * rstd * gv.y + bv.y;
    o4.z = (h.z - mean) * rstd * gv.z + bv.z;
    o4.w = (h.w - mean) * rstd * gv.w + bv.w;
    reinterpret_cast<float4*>(out + off)[tid] = o4;
}

// ---------------------------------------------------------------------------
// launch
// ---------------------------------------------------------------------------
extern "C" void kernel_launch(void* const* d_in, const int* in_sizes, int n_in,
                              void* d_out, int out_size)
{
    const float* x     = (const float*)d_in[0];  // [4,4096,512]
    const float* Wq    = (const float*)d_in[1];  // [512,512]
    const float* Wk    = (const float*)d_in[2];
    const float* Wv    = (const float*)d_in[3];
    const float* gamma = (const float*)d_in[4];
    const float* beta  = (const float*)d_in[5];
    float* out = (float*)d_out;

    float *Wt, *QK, *Vt, *S, *P1;
    cudaGetSymbolAddress((void**)&Wt, g_Wt);
    cudaGetSymbolAddress((void**)&QK, g_QK);
    cudaGetSymbolAddress((void**)&Vt, g_Vt);
    cudaGetSymbolAddress((void**)&S,  g_S);
    cudaGetSymbolAddress((void**)&P1, g_P1);

    float* Q  = QK;                         // [16384,512], later reused as att
    float* Kp = QK + 16384ll * 512;         // [16384,512]

    // 1) transpose weights (Wt[z] = W_z^T, row-major [e][d])
    transpose512<<<dim3(16, 16, 3), dim3(32, 8)>>>(Wq, Wk, Wv);

    // 2) Q|K = X @ {Wq,Wk} in one launch (z selects weight + output)
    //    M=16384 N=512 K=512.  B[n][k] = Wt_z[n*512+k]
    gemm_tf32<<<dim3(4, 128, 2), 128>>>(x, 512, 0, 0,
                                        Wt, 512, 512ll * 512, 0,
                                        QK, 16384ll * 512,
                                        nullptr, 0,
                                        512, 512, 1.0f);
    // 3) Vt = Wv^T @ X^T : M=512 N=16384 K=512.  B[n][k] = x[n*512+k]
    gemm_tf32<<<dim3(128, 4, 1), 128>>>(Wt + 2 * 512 * 512, 512, 0, 0,
                                        x, 512, 0, 0,
                                        Vt, 0,
                                        nullptr, 0,
                                        16384, 512, 1.0f);

    // 4) attention: 4 chunk passes, batches via z; PV split-K=2 via z>>2.
    const float inv_sqrt_d = 0.04419417382415922f;   // 1/sqrt(512)
    for (int c = 0; c < 4; c++) {
        float* Qc = Q + (long long)c * CHUNK * 512;
        // S[b] = (Q_chunk[b] K_b^T) / sqrt(D) : M=CHUNK N=4096 K=512, z=batch
        gemm_tf32<<<dim3(32, CHUNK / BM, 4), 128>>>(
            Qc, 512, 4096ll * 512, 0,
            Kp, 512, 4096ll * 512, 0,
            S, (long long)CHUNK * 4096,
            nullptr, 0,
            4096, 512, inv_sqrt_d);
        // row softmax in place over all 4 batches of this chunk
        softmax4096<<<4 * CHUNK, 256>>>(S);
        // att_chunk[b] = P[b] @ V_b, split-K=2 : M=CHUNK N=512 K=2048 per half
        //   z = b + 4*kh; kh=1 writes partial into P1 (batch stride CHUNK*512)
        //   B[n=e][k=m] = Vt[e*16384 + b*4096 + kh*2048 + m]
        gemm_tf32<<<dim3(4, CHUNK / BM, 8), 128>>>(
            S, 4096, (long long)CHUNK * 4096, 2048,
            Vt, 16384, 4096, 2048,
            Qc, 4096ll * 512,
            P1, (long long)CHUNK * 512,
            512, 2048, 1.0f);
        // fold the second k-half into att
        add_partial<<<dim3(CHUNK * 512 / 4 / 256, 4), 256>>>(
            Qc, 4096ll * 512, P1, (long long)CHUNK * 512);
    }

    // 5) residual + LayerNorm (att lives in Q)
    add_ln<<<16384, 128>>>(Q, x, gamma, beta, out);
}